// round 4
// baseline (speedup 1.0000x reference)
#include <cuda_runtime.h>
#include <cstdint>

typedef unsigned long long ULL;

// ---------------- problem constants ----------------
#define Bb    128
#define Tt    512
#define NOBS  256
#define Hh    512
#define G4    2048            // 4*H
#define NACT  32
#define MTOT  (Bb * Tt)       // 65536

// SW128-style swizzle on a byte offset (bits[4:6] ^= bits[7:9])
#define SWZ(off) ((off) ^ (((off) >> 3) & 0x70u))

// ---------------- device scratch ----------------
__device__ float g_xg  [(size_t)MTOT * G4];    // obs @ Wx, row-major (B*T, 4H)
__device__ float g_ysT [(size_t)Hh * MTOT];    // LSTM hidden, TRANSPOSED (H, B*T)
__device__ float g_a1T [(size_t)Hh * MTOT];    // MLP1 out, TRANSPOSED
__device__ float g_a2  [(size_t)MTOT * Hh];    // MLP2 out, row-major
__device__ float g_obsT[(size_t)NOBS * MTOT];  // obs transposed
__device__ ULL   g_Wxp [(size_t)NOBS * G4];    // dup-packed weights
__device__ ULL   g_W1p [(size_t)Hh * Hh];
__device__ ULL   g_W2p [(size_t)Hh * Hh];
__device__ float g_hT  [2][Hh * Bb];           // double-buffered h, transposed [H][B]
__device__ unsigned g_arrive[128];             // monotonic per-CTA barrier flags

// ---------------- f32x2 / cp.async helpers ----------------
__device__ __forceinline__ ULL ffma2(ULL a, ULL b, ULL c) {
    ULL d;
    asm("fma.rn.f32x2 %0, %1, %2, %3;" : "=l"(d) : "l"(a), "l"(b), "l"(c));
    return d;
}
__device__ __forceinline__ ULL add2(ULL a, ULL b) {
    ULL d;
    asm("add.rn.f32x2 %0, %1, %2;" : "=l"(d) : "l"(a), "l"(b));
    return d;
}
__device__ __forceinline__ ULL pack2(float lo, float hi) {
    ULL d;
    asm("mov.b64 %0, {%1, %2};" : "=l"(d) : "f"(lo), "f"(hi));
    return d;
}
__device__ __forceinline__ void unpack2(ULL v, float& lo, float& hi) {
    asm("mov.b64 {%0, %1}, %2;" : "=f"(lo), "=f"(hi) : "l"(v));
}
__device__ __forceinline__ float sigmoidf_(float x) {
    return 1.0f / (1.0f + expf(-x));
}
__device__ __forceinline__ unsigned sptr(const void* p) {
    return (unsigned)__cvta_generic_to_shared(p);
}
#define CP16(d, s)  asm volatile("cp.async.cg.shared.global [%0], [%1], 16;" :: "r"(d), "l"(s) : "memory")
#define CP_COMMIT() asm volatile("cp.async.commit_group;" ::: "memory")
#define CP_WAIT1()  asm volatile("cp.async.wait_group 1;" ::: "memory")
#define CP_WAIT0()  asm volatile("cp.async.wait_group 0;" ::: "memory")

// =====================================================================================
// Pre-pass kernels
// =====================================================================================
__global__ __launch_bounds__(256)
void pack_dup(const float* __restrict__ W, ULL* __restrict__ Wp, int n) {
    int i = blockIdx.x * 256 + threadIdx.x;
    if (i < n) { float w = W[i]; Wp[i] = pack2(w, w); }
}

__global__ __launch_bounds__(256)
void transpose_k(const float* __restrict__ A, float* __restrict__ AT, int M, int K) {
    __shared__ float t[32][33];
    int m0 = blockIdx.x * 32, k0 = blockIdx.y * 32;
    int x = threadIdx.x & 31, y = threadIdx.x >> 5;   // y: 0..7
    #pragma unroll
    for (int i = 0; i < 32; i += 8)
        t[y + i][x] = A[(size_t)(m0 + y + i) * K + k0 + x];
    __syncthreads();
    #pragma unroll
    for (int i = 0; i < 32; i += 8)
        AT[(size_t)(k0 + y + i) * M + m0 + x] = t[x][y + i];
}

// =====================================================================================
// Pipelined GEMM: C = act(AT^T @ Wp + bias), AT is (K,M), Wp dup-packed (K,N).
// 128x128x16, 8x8 micro-tile, cp.async double-buffered, zero in-kernel reshaping.
// ACT: 0=none(no bias) 1=bias+relu ; TOUT: 0=row-major C(M,N), 1=transposed C(N,M)
// =====================================================================================
template <int ACT, int TOUT>
__global__ __launch_bounds__(256, 2)
void gemm_p(const float* __restrict__ AT, const ULL* __restrict__ Wp,
            const float* __restrict__ bias, float* __restrict__ C,
            int M, int N, int K)
{
    __shared__ __align__(16)  float As[2][16][128];   // (K,M) chunk, raw
    __shared__ __align__(128) char  Wd[2][16384];     // dup-packed W, swizzled

    const int tid = threadIdx.x;
    const int tx  = tid & 15;
    const int ty  = tid >> 4;
    const int m0  = blockIdx.y * 128;
    const int n0  = blockIdx.x * 128;
    const int r0  = ty * 8;
    const int c0  = tx * 8;
    const int nK  = K / 16;

    ULL acc[4][8];
    #pragma unroll
    for (int i = 0; i < 4; i++)
        #pragma unroll
        for (int j = 0; j < 8; j++) acc[i][j] = 0ULL;

    auto fill = [&](int kc, int s) {
        // A chunk: 16 rows x 128 floats = 512 x 16B
        #pragma unroll
        for (int q = 0; q < 2; q++) {
            int f = tid + 256 * q;
            int k = f >> 5, u = f & 31;
            CP16(sptr(&As[s][k][u * 4]),
                 &AT[(size_t)(kc * 16 + k) * M + m0 + u * 4]);
        }
        // W chunk: 16 rows x 128 ULL = 1024 x 16B, swizzled dst
        unsigned wbase = sptr(&Wd[s][0]);
        #pragma unroll
        for (int q = 0; q < 4; q++) {
            int f = tid + 256 * q;
            int k = f >> 6, u = f & 63;
            unsigned off = (unsigned)(k * 1024 + u * 16);
            CP16(wbase + SWZ(off),
                 &Wp[(size_t)(kc * 16 + k) * N + n0 + u * 2]);
        }
    };

    fill(0, 0);
    CP_COMMIT();

    for (int kc = 0; kc < nK; kc++) {
        if (kc + 1 < nK) { fill(kc + 1, (kc + 1) & 1); CP_COMMIT(); CP_WAIT1(); }
        else             { CP_WAIT0(); }
        __syncthreads();
        const int s = kc & 1;
        #pragma unroll
        for (int kk = 0; kk < 16; kk++) {
            ulonglong2 a01 = *reinterpret_cast<const ulonglong2*>(&As[s][kk][r0]);
            ulonglong2 a23 = *reinterpret_cast<const ulonglong2*>(&As[s][kk][r0 + 4]);
            ULL a[4] = {a01.x, a01.y, a23.x, a23.y};
            ULL w[8];
            #pragma unroll
            for (int q = 0; q < 4; q++) {
                unsigned off = (unsigned)(kk * 1024 + (c0 + 2 * q) * 8);
                ulonglong2 wv = *reinterpret_cast<const ulonglong2*>(&Wd[s][SWZ(off)]);
                w[2 * q]     = wv.x;
                w[2 * q + 1] = wv.y;
            }
            #pragma unroll
            for (int i = 0; i < 4; i++)
                #pragma unroll
                for (int j = 0; j < 8; j++)
                    acc[i][j] = ffma2(a[i], w[j], acc[i][j]);
        }
        __syncthreads();
    }

    // ---- epilogue ----
    float v[8][8];   // v[m-local][j]
    #pragma unroll
    for (int i = 0; i < 4; i++)
        #pragma unroll
        for (int j = 0; j < 8; j++)
            unpack2(acc[i][j], v[2 * i][j], v[2 * i + 1][j]);

    if constexpr (ACT == 1) {
        #pragma unroll
        for (int j = 0; j < 8; j++) {
            float bc = bias[n0 + c0 + j];
            #pragma unroll
            for (int m = 0; m < 8; m++) v[m][j] = fmaxf(v[m][j] + bc, 0.0f);
        }
    }

    if constexpr (TOUT == 0) {
        #pragma unroll
        for (int m = 0; m < 8; m++) {
            float4 o0 = {v[m][0], v[m][1], v[m][2], v[m][3]};
            float4 o1 = {v[m][4], v[m][5], v[m][6], v[m][7]};
            size_t row = (size_t)(m0 + r0 + m);
            *reinterpret_cast<float4*>(&C[row * N + n0 + c0])     = o0;
            *reinterpret_cast<float4*>(&C[row * N + n0 + c0 + 4]) = o1;
        }
    } else {
        #pragma unroll
        for (int j = 0; j < 8; j++) {
            float4 lo = {v[0][j], v[1][j], v[2][j], v[3][j]};
            float4 hi = {v[4][j], v[5][j], v[6][j], v[7][j]};
            size_t col = (size_t)(n0 + c0 + j);
            *reinterpret_cast<float4*>(&C[col * M + m0 + r0])     = lo;
            *reinterpret_cast<float4*>(&C[col * M + m0 + r0 + 4]) = hi;
        }
    }
}

// =====================================================================================
// Head GEMM (N=32): C = 0.5*(tanh(A@W+b)*(amax-amin)+(amax+amin)); A row-major.
// =====================================================================================
__global__ __launch_bounds__(256)
void gemm_head(const float* __restrict__ A, const float* __restrict__ W,
               const float* __restrict__ bias, float* __restrict__ C,
               int M, int N, int K,
               const float* __restrict__ amin, const float* __restrict__ amax)
{
    __shared__ __align__(16) float Ast[16][136];
    __shared__ __align__(16) ULL   Wd[16][32];

    const int tid = threadIdx.x;
    const int tx  = tid % 8;
    const int ty  = tid / 8;
    const int m0  = blockIdx.y * 128;
    const int n0  = blockIdx.x * 32;
    const int r0  = ty * 4;
    const int c0  = tx * 4;

    ULL acc[2][4];
    #pragma unroll
    for (int i = 0; i < 2; i++)
        #pragma unroll
        for (int j = 0; j < 4; j++) acc[i][j] = 0ULL;

    for (int kc = 0; kc < K; kc += 16) {
        #pragma unroll
        for (int q = 0; q < 2; q++) {
            int idx = tid + 256 * q;
            int m   = idx >> 2;
            int kq  = idx & 3;
            float4 vv = *reinterpret_cast<const float4*>(
                &A[(size_t)(m0 + m) * K + kc + kq * 4]);
            Ast[kq * 4 + 0][m] = vv.x;
            Ast[kq * 4 + 1][m] = vv.y;
            Ast[kq * 4 + 2][m] = vv.z;
            Ast[kq * 4 + 3][m] = vv.w;
        }
        #pragma unroll
        for (int q = 0; q < 2; q++) {
            int idx = tid + 256 * q;
            if (idx < 16 * 32) {
                int k = idx >> 5, c = idx & 31;
                float w = W[(size_t)(kc + k) * N + n0 + c];
                Wd[k][c] = pack2(w, w);
            }
        }
        __syncthreads();

        #pragma unroll
        for (int kk = 0; kk < 16; kk++) {
            ULL a[2];
            a[0] = *reinterpret_cast<const ULL*>(&Ast[kk][r0]);
            a[1] = *reinterpret_cast<const ULL*>(&Ast[kk][r0 + 2]);
            ULL w[4];
            #pragma unroll
            for (int j = 0; j < 4; j++) w[j] = Wd[kk][c0 + j];
            #pragma unroll
            for (int i = 0; i < 2; i++)
                #pragma unroll
                for (int j = 0; j < 4; j++)
                    acc[i][j] = ffma2(a[i], w[j], acc[i][j]);
        }
        __syncthreads();
    }

    float bc[4], sA[4], sB[4];
    #pragma unroll
    for (int j = 0; j < 4; j++) {
        bc[j] = bias[n0 + c0 + j];
        float lo = amin[n0 + c0 + j], hi = amax[n0 + c0 + j];
        sA[j] = 0.5f * (hi - lo);
        sB[j] = 0.5f * (hi + lo);
    }

    #pragma unroll
    for (int i = 0; i < 2; i++) {
        float vlo[4], vhi[4];
        #pragma unroll
        for (int j = 0; j < 4; j++) unpack2(acc[i][j], vlo[j], vhi[j]);
        int row = m0 + r0 + 2 * i;
        #pragma unroll
        for (int h = 0; h < 2; h++) {
            float* vv = (h == 0) ? vlo : vhi;
            float ov[4];
            #pragma unroll
            for (int j = 0; j < 4; j++) {
                float x = tanhf(vv[j] + bc[j]);
                ov[j] = x * sA[j] + sB[j];
            }
            float4 o = {ov[0], ov[1], ov[2], ov[3]};
            *reinterpret_cast<float4*>(&C[(size_t)(row + h) * N + n0 + c0]) = o;
        }
    }
}

// =====================================================================================
// Persistent LSTM scan v3: 128 CTAs x 512 threads. CTA owns 16 z-cols.
// K split in halves across thread groups; cp.async.cg staging (L2-coherent, pipelined);
// distributed flag grid barrier; writes ys TRANSPOSED.
// =====================================================================================
// dyn smem: Wsm 512*16*8=65536 | Asm 2*2*32*128*4=65536 | psm 256*4*8=8192
//           zsm 128*18*4=9216 | csm 2048 | bsm 64   => 150592 B
#define SCAN_SMEM (65536 + 65536 + 8192 + 9216 + 2048 + 64)

__device__ __forceinline__ void gbar(unsigned target) {
    __syncthreads();
    if (threadIdx.x == 0) {
        __threadfence();
        ((volatile unsigned*)g_arrive)[blockIdx.x] = target;
    }
    if (threadIdx.x < 128) {
        while (((volatile unsigned*)g_arrive)[threadIdx.x] < target) { __nanosleep(16); }
        __threadfence();
    }
    __syncthreads();
}

__global__ __launch_bounds__(512, 1)
void scan_kernel(const float* __restrict__ xg, const float* __restrict__ Wh,
                 const float* __restrict__ b,  const float* __restrict__ h0,
                 const float* __restrict__ c0,
                 float* __restrict__ ysT, float* __restrict__ hOut,
                 float* __restrict__ cOut)
{
    extern __shared__ __align__(128) char smraw[];
    ULL   (*Wsm)[16]           = reinterpret_cast<ULL(*)[16]>(smraw);
    float (*Asm)[2][32][128]   = reinterpret_cast<float(*)[2][32][128]>(smraw + 65536);
    ULL   (*psm)[4]            = reinterpret_cast<ULL(*)[4]>(smraw + 131072);
    float (*zsm)[18]           = reinterpret_cast<float(*)[18]>(smraw + 139264);
    float (*csm)[4]            = reinterpret_cast<float(*)[4]>(smraw + 148480);
    float *bsm                 = reinterpret_cast<float*>(smraw + 150528);

    const int tid  = threadIdx.x;
    const int cb   = blockIdx.x;
    const int j0   = cb * 4;
    const int half = tid >> 8;          // K-half
    const int s    = tid & 255;
    const int cp   = s & 7;             // col-pair
    const int rq   = s >> 3;            // row-quad
    const int cA   = 2 * cp;
    const int cBc  = 2 * cp + 1;
    const int zcA  = (cA  >> 2) * Hh + j0 + (cA  & 3);
    const int zcB  = (cBc >> 2) * Hh + j0 + (cBc & 3);
    const int kbase = half * 256;

    const unsigned base = ((volatile unsigned*)g_arrive)[cb];

    // ---- resident dup-packed Wh slice ----
    for (int idx = tid; idx < 512 * 16; idx += 512) {
        int k = idx >> 4, c = idx & 15;
        int zcol = (c >> 2) * Hh + j0 + (c & 3);
        float w = Wh[(size_t)k * G4 + zcol];
        Wsm[k][c] = pack2(w, w);
    }
    if (tid < 16) bsm[tid] = b[(tid >> 2) * Hh + j0 + (tid & 3)];
    {
        int r = tid >> 2, jj = tid & 3;
        csm[r][jj] = c0[r * Hh + j0 + jj];
    }
    // ---- init transposed h buffer slot 0 ----
    for (int idx = cb * 512 + tid; idx < Hh * Bb; idx += 128 * 512) {
        int j = idx >> 7, r = idx & 127;
        g_hT[0][idx] = h0[r * Hh + j];
    }
    gbar(base + 1);

    for (int t = 0; t < Tt; t++) {
        const float* hs = g_hT[t & 1];
        float*       hd = g_hT[(t + 1) & 1];

        // ---- xg prefetch (half 0 only; folded in at epilogue) ----
        float xv[4][2];
        if (half == 0) {
            #pragma unroll
            for (int rr = 0; rr < 4; rr++) {
                size_t bi = ((size_t)(4 * rq + rr) * Tt + t) * G4;
                xv[rr][0] = __ldg(&xg[bi + zcA]);
                xv[rr][1] = __ldg(&xg[bi + zcB]);
            }
        }

        ULL acc00 = 0, acc01 = 0, acc10 = 0, acc11 = 0;

        auto stage = [&](int i, int buf) {
            #pragma unroll
            for (int q = 0; q < 4; q++) {
                int f  = tid + 512 * q;          // 0..2047 (16B units)
                int hf = f >> 10;
                int u  = f & 1023;
                int k  = u >> 5, c = u & 31;
                CP16(sptr(&Asm[buf][hf][k][c * 4]),
                     hs + ((hf * 256 + i * 32 + k) << 7) + c * 4);
            }
        };

        stage(0, 0);
        CP_COMMIT();
        for (int i = 0; i < 8; i++) {
            if (i < 7) { stage(i + 1, (i + 1) & 1); CP_COMMIT(); CP_WAIT1(); }
            else       { CP_WAIT0(); }
            __syncthreads();
            const int buf = i & 1;
            #pragma unroll
            for (int kk = 0; kk < 32; kk++) {
                ulonglong2 a = *reinterpret_cast<const ulonglong2*>(&Asm[buf][half][kk][4 * rq]);
                ulonglong2 w = *reinterpret_cast<const ulonglong2*>(&Wsm[kbase + i * 32 + kk][cA]);
                acc00 = ffma2(a.x, w.x, acc00);
                acc01 = ffma2(a.x, w.y, acc01);
                acc10 = ffma2(a.y, w.x, acc10);
                acc11 = ffma2(a.y, w.y, acc11);
            }
            __syncthreads();
        }

        // ---- cross-half reduction + z epilogue ----
        if (half == 1) {
            psm[s][0] = acc00; psm[s][1] = acc01;
            psm[s][2] = acc10; psm[s][3] = acc11;
        }
        __syncthreads();
        if (half == 0) {
            acc00 = add2(acc00, psm[s][0]);
            acc01 = add2(acc01, psm[s][1]);
            acc10 = add2(acc10, psm[s][2]);
            acc11 = add2(acc11, psm[s][3]);
            float bA = bsm[cA], bB = bsm[cBc];
            float lo, hi;
            unpack2(acc00, lo, hi);
            zsm[4 * rq + 0][cA]  = lo + xv[0][0] + bA;
            zsm[4 * rq + 1][cA]  = hi + xv[1][0] + bA;
            unpack2(acc01, lo, hi);
            zsm[4 * rq + 0][cBc] = lo + xv[0][1] + bB;
            zsm[4 * rq + 1][cBc] = hi + xv[1][1] + bB;
            unpack2(acc10, lo, hi);
            zsm[4 * rq + 2][cA]  = lo + xv[2][0] + bA;
            zsm[4 * rq + 3][cA]  = hi + xv[3][0] + bA;
            unpack2(acc11, lo, hi);
            zsm[4 * rq + 2][cBc] = lo + xv[2][1] + bB;
            zsm[4 * rq + 3][cBc] = hi + xv[3][1] + bB;
        }
        __syncthreads();

        // ---- gate update: 512 elems, 1/thread ----
        {
            int r = tid >> 2, jj = tid & 3;
            float zi = zsm[r][0  + jj];
            float zf = zsm[r][4  + jj];
            float zg = zsm[r][8  + jj];
            float zo = zsm[r][12 + jj];
            float cc = csm[r][jj];
            float cn = sigmoidf_(zf) * cc + sigmoidf_(zi) * tanhf(zg);
            float hn = sigmoidf_(zo) * tanhf(cn);
            csm[r][jj] = cn;
            hd[(j0 + jj) * Bb + r] = hn;
            ysT[(size_t)(j0 + jj) * MTOT + r * Tt + t] = hn;
            if (t == Tt - 1) hOut[r * Hh + j0 + jj] = hn;
        }

        gbar(base + 2 + (unsigned)t);
    }

    {
        int r = tid >> 2, jj = tid & 3;
        cOut[r * Hh + j0 + jj] = csm[r][jj];
    }
}

// =====================================================================================
extern "C" void kernel_launch(void* const* d_in, const int* in_sizes, int n_in,
                              void* d_out, int out_size)
{
    const float* obs  = (const float*)d_in[0];
    const float* h0   = (const float*)d_in[1];
    const float* c0   = (const float*)d_in[2];
    const float* Wx   = (const float*)d_in[3];
    const float* Wh   = (const float*)d_in[4];
    const float* b    = (const float*)d_in[5];
    const float* W1   = (const float*)d_in[6];
    const float* b1   = (const float*)d_in[7];
    const float* W2   = (const float*)d_in[8];
    const float* b2   = (const float*)d_in[9];
    const float* Wo   = (const float*)d_in[10];
    const float* bo   = (const float*)d_in[11];
    const float* amin = (const float*)d_in[12];
    const float* amax = (const float*)d_in[13];

    float* out        = (float*)d_out;
    float* out_action = out;
    float* out_h      = out + (size_t)MTOT * NACT;
    float* out_c      = out_h + (size_t)Bb * Hh;

    float *p_xg, *p_ysT, *p_a1T, *p_a2, *p_obsT;
    ULL   *p_Wxp, *p_W1p, *p_W2p;
    cudaGetSymbolAddress((void**)&p_xg,   g_xg);
    cudaGetSymbolAddress((void**)&p_ysT,  g_ysT);
    cudaGetSymbolAddress((void**)&p_a1T,  g_a1T);
    cudaGetSymbolAddress((void**)&p_a2,   g_a2);
    cudaGetSymbolAddress((void**)&p_obsT, g_obsT);
    cudaGetSymbolAddress((void**)&p_Wxp,  g_Wxp);
    cudaGetSymbolAddress((void**)&p_W1p,  g_W1p);
    cudaGetSymbolAddress((void**)&p_W2p,  g_W2p);

    cudaFuncSetAttribute(scan_kernel,
                         cudaFuncAttributeMaxDynamicSharedMemorySize, SCAN_SMEM);

    // ---- pre-pass: transpose obs, dup-pack weights ----
    {
        dim3 g(MTOT / 32, NOBS / 32);
        transpose_k<<<g, 256>>>(obs, p_obsT, MTOT, NOBS);
        pack_dup<<<(NOBS * G4 + 255) / 256, 256>>>(Wx, p_Wxp, NOBS * G4);
        pack_dup<<<(Hh * Hh + 255) / 256, 256>>>(W1, p_W1p, Hh * Hh);
        pack_dup<<<(Hh * Hh + 255) / 256, 256>>>(W2, p_W2p, Hh * Hh);
    }
    // 1) xg = obs @ Wx   (row-major out)
    {
        dim3 grid(G4 / 128, MTOT / 128);
        gemm_p<0, 0><<<grid, 256>>>(p_obsT, p_Wxp, nullptr, p_xg, MTOT, G4, NOBS);
    }
    // 2) LSTM scan (persistent, 128 CTAs x 512 threads) -> ysT
    scan_kernel<<<128, 512, SCAN_SMEM>>>(p_xg, Wh, b, h0, c0, p_ysT, out_h, out_c);
    // 3) a1T = relu(ys @ W1 + b1)^T
    {
        dim3 grid(Hh / 128, MTOT / 128);
        gemm_p<1, 1><<<grid, 256>>>(p_ysT, p_W1p, b1, p_a1T, MTOT, Hh, Hh);
    }
    // 4) a2 = relu(a1 @ W2 + b2)   (row-major out)
    {
        dim3 grid(Hh / 128, MTOT / 128);
        gemm_p<1, 0><<<grid, 256>>>(p_a1T, p_W2p, b2, p_a2, MTOT, Hh, Hh);
    }
    // 5) action head
    {
        dim3 grid(NACT / 32, MTOT / 128);
        gemm_head<<<grid, 256>>>(p_a2, Wo, bo, out_action, MTOT, NACT, Hh, amin, amax);
    }
    (void)in_sizes; (void)n_in; (void)out_size;
}

// round 10
// speedup vs baseline: 1.0339x; 1.0339x over previous
#include <cuda_runtime.h>
#include <cstdint>

typedef unsigned long long ULL;

// ---------------- problem constants ----------------
#define Bb    128
#define Tt    512
#define NOBS  256
#define Hh    512
#define G4    2048            // 4*H
#define NACT  32
#define MTOT  (Bb * Tt)       // 65536

// SW128-style swizzle on a byte offset (bits[4:6] ^= bits[7:9])
#define SWZ(off) ((off) ^ (((off) >> 3) & 0x70u))

// ---------------- device scratch ----------------
__device__ float g_xg  [(size_t)MTOT * G4];    // obs @ Wx, row-major (B*T, 4H)
__device__ float g_ys  [(size_t)MTOT * Hh];    // LSTM hidden, row-major (B*T, H)
__device__ float g_ysT [(size_t)Hh * MTOT];    // transposed for MLP1
__device__ float g_a1T [(size_t)Hh * MTOT];    // MLP1 out, TRANSPOSED
__device__ float g_a2  [(size_t)MTOT * Hh];    // MLP2 out, row-major
__device__ float g_obsT[(size_t)NOBS * MTOT];  // obs transposed
__device__ ULL   g_Wxp [(size_t)NOBS * G4];    // dup-packed weights
__device__ ULL   g_W1p [(size_t)Hh * Hh];
__device__ ULL   g_W2p [(size_t)Hh * Hh];
__device__ float g_hT  [2][Hh * Bb];           // double-buffered h, transposed [H][B]
__device__ unsigned g_arrive[128];             // monotonic per-CTA barrier flags

// ---------------- f32x2 / cp.async helpers ----------------
__device__ __forceinline__ ULL ffma2(ULL a, ULL b, ULL c) {
    ULL d;
    asm("fma.rn.f32x2 %0, %1, %2, %3;" : "=l"(d) : "l"(a), "l"(b), "l"(c));
    return d;
}
__device__ __forceinline__ ULL add2(ULL a, ULL b) {
    ULL d;
    asm("add.rn.f32x2 %0, %1, %2;" : "=l"(d) : "l"(a), "l"(b));
    return d;
}
__device__ __forceinline__ ULL pack2(float lo, float hi) {
    ULL d;
    asm("mov.b64 %0, {%1, %2};" : "=l"(d) : "f"(lo), "f"(hi));
    return d;
}
__device__ __forceinline__ void unpack2(ULL v, float& lo, float& hi) {
    asm("mov.b64 {%0, %1}, %2;" : "=f"(lo), "=f"(hi) : "l"(v));
}
__device__ __forceinline__ float sigmoidf_(float x) {
    return 1.0f / (1.0f + expf(-x));
}
__device__ __forceinline__ unsigned sptr(const void* p) {
    return (unsigned)__cvta_generic_to_shared(p);
}
#define CP16(d, s)  asm volatile("cp.async.cg.shared.global [%0], [%1], 16;" :: "r"(d), "l"(s) : "memory")
#define CP_COMMIT() asm volatile("cp.async.commit_group;" ::: "memory")
#define CP_WAIT1()  asm volatile("cp.async.wait_group 1;" ::: "memory")
#define CP_WAIT0()  asm volatile("cp.async.wait_group 0;" ::: "memory")

// =====================================================================================
// Pre-pass kernels
// =====================================================================================
__global__ __launch_bounds__(256)
void pack_dup(const float* __restrict__ W, ULL* __restrict__ Wp, int n) {
    int i = blockIdx.x * 256 + threadIdx.x;
    if (i < n) { float w = W[i]; Wp[i] = pack2(w, w); }
}

__global__ __launch_bounds__(256)
void transpose_k(const float* __restrict__ A, float* __restrict__ AT, int M, int K) {
    __shared__ float t[32][33];
    int m0 = blockIdx.x * 32, k0 = blockIdx.y * 32;
    int x = threadIdx.x & 31, y = threadIdx.x >> 5;   // y: 0..7
    #pragma unroll
    for (int i = 0; i < 32; i += 8)
        t[y + i][x] = A[(size_t)(m0 + y + i) * K + k0 + x];
    __syncthreads();
    #pragma unroll
    for (int i = 0; i < 32; i += 8)
        AT[(size_t)(k0 + y + i) * M + m0 + x] = t[x][y + i];
}

// =====================================================================================
// Pipelined GEMM: C = act(AT^T @ Wp + bias), AT is (K,M), Wp dup-packed (K,N).
// 128x128x16, 8x8 micro-tile, cp.async double-buffered.
// ACT: 0=none(no bias) 1=bias+relu ; TOUT: 0=row-major C(M,N), 1=transposed C(N,M)
// NOTE: no min-blocks clause — forcing 2 CTAs/SM capped regs at 128 and spilled (R4).
// =====================================================================================
template <int ACT, int TOUT>
__global__ __launch_bounds__(256)
void gemm_p(const float* __restrict__ AT, const ULL* __restrict__ Wp,
            const float* __restrict__ bias, float* __restrict__ C,
            int M, int N, int K)
{
    __shared__ __align__(16)  float As[2][16][128];   // (K,M) chunk, raw
    __shared__ __align__(128) char  Wd[2][16384];     // dup-packed W, swizzled

    const int tid = threadIdx.x;
    const int tx  = tid & 15;
    const int ty  = tid >> 4;
    const int m0  = blockIdx.y * 128;
    const int n0  = blockIdx.x * 128;
    const int r0  = ty * 8;
    const int c0  = tx * 8;
    const int nK  = K / 16;

    ULL acc[4][8];
    #pragma unroll
    for (int i = 0; i < 4; i++)
        #pragma unroll
        for (int j = 0; j < 8; j++) acc[i][j] = 0ULL;

    auto fill = [&](int kc, int s) {
        #pragma unroll
        for (int q = 0; q < 2; q++) {
            int f = tid + 256 * q;
            int k = f >> 5, u = f & 31;
            CP16(sptr(&As[s][k][u * 4]),
                 &AT[(size_t)(kc * 16 + k) * M + m0 + u * 4]);
        }
        unsigned wbase = sptr(&Wd[s][0]);
        #pragma unroll
        for (int q = 0; q < 4; q++) {
            int f = tid + 256 * q;
            int k = f >> 6, u = f & 63;
            unsigned off = (unsigned)(k * 1024 + u * 16);
            CP16(wbase + SWZ(off),
                 &Wp[(size_t)(kc * 16 + k) * N + n0 + u * 2]);
        }
    };

    fill(0, 0);
    CP_COMMIT();

    for (int kc = 0; kc < nK; kc++) {
        if (kc + 1 < nK) { fill(kc + 1, (kc + 1) & 1); CP_COMMIT(); CP_WAIT1(); }
        else             { CP_WAIT0(); }
        __syncthreads();
        const int s = kc & 1;
        #pragma unroll
        for (int kk = 0; kk < 16; kk++) {
            ulonglong2 a01 = *reinterpret_cast<const ulonglong2*>(&As[s][kk][r0]);
            ulonglong2 a23 = *reinterpret_cast<const ulonglong2*>(&As[s][kk][r0 + 4]);
            ULL a[4] = {a01.x, a01.y, a23.x, a23.y};
            ULL w[8];
            #pragma unroll
            for (int q = 0; q < 4; q++) {
                unsigned off = (unsigned)(kk * 1024 + (c0 + 2 * q) * 8);
                ulonglong2 wv = *reinterpret_cast<const ulonglong2*>(&Wd[s][SWZ(off)]);
                w[2 * q]     = wv.x;
                w[2 * q + 1] = wv.y;
            }
            #pragma unroll
            for (int i = 0; i < 4; i++)
                #pragma unroll
                for (int j = 0; j < 8; j++)
                    acc[i][j] = ffma2(a[i], w[j], acc[i][j]);
        }
        __syncthreads();
    }

    // ---- epilogue ----
    float v[8][8];
    #pragma unroll
    for (int i = 0; i < 4; i++)
        #pragma unroll
        for (int j = 0; j < 8; j++)
            unpack2(acc[i][j], v[2 * i][j], v[2 * i + 1][j]);

    if constexpr (ACT == 1) {
        #pragma unroll
        for (int j = 0; j < 8; j++) {
            float bc = bias[n0 + c0 + j];
            #pragma unroll
            for (int m = 0; m < 8; m++) v[m][j] = fmaxf(v[m][j] + bc, 0.0f);
        }
    }

    if constexpr (TOUT == 0) {
        #pragma unroll
        for (int m = 0; m < 8; m++) {
            float4 o0 = {v[m][0], v[m][1], v[m][2], v[m][3]};
            float4 o1 = {v[m][4], v[m][5], v[m][6], v[m][7]};
            size_t row = (size_t)(m0 + r0 + m);
            *reinterpret_cast<float4*>(&C[row * N + n0 + c0])     = o0;
            *reinterpret_cast<float4*>(&C[row * N + n0 + c0 + 4]) = o1;
        }
    } else {
        #pragma unroll
        for (int j = 0; j < 8; j++) {
            float4 lo = {v[0][j], v[1][j], v[2][j], v[3][j]};
            float4 hi = {v[4][j], v[5][j], v[6][j], v[7][j]};
            size_t col = (size_t)(n0 + c0 + j);
            *reinterpret_cast<float4*>(&C[col * M + m0 + r0])     = lo;
            *reinterpret_cast<float4*>(&C[col * M + m0 + r0 + 4]) = hi;
        }
    }
}

// =====================================================================================
// Head GEMM (N=32): C = 0.5*(tanh(A@W+b)*(amax-amin)+(amax+amin)); A row-major.
// =====================================================================================
__global__ __launch_bounds__(256)
void gemm_head(const float* __restrict__ A, const float* __restrict__ W,
               const float* __restrict__ bias, float* __restrict__ C,
               int M, int N, int K,
               const float* __restrict__ amin, const float* __restrict__ amax)
{
    __shared__ __align__(16) float Ast[16][136];
    __shared__ __align__(16) ULL   Wd[16][32];

    const int tid = threadIdx.x;
    const int tx  = tid % 8;
    const int ty  = tid / 8;
    const int m0  = blockIdx.y * 128;
    const int n0  = blockIdx.x * 32;
    const int r0  = ty * 4;
    const int c0  = tx * 4;

    ULL acc[2][4];
    #pragma unroll
    for (int i = 0; i < 2; i++)
        #pragma unroll
        for (int j = 0; j < 4; j++) acc[i][j] = 0ULL;

    for (int kc = 0; kc < K; kc += 16) {
        #pragma unroll
        for (int q = 0; q < 2; q++) {
            int idx = tid + 256 * q;
            int m   = idx >> 2;
            int kq  = idx & 3;
            float4 vv = *reinterpret_cast<const float4*>(
                &A[(size_t)(m0 + m) * K + kc + kq * 4]);
            Ast[kq * 4 + 0][m] = vv.x;
            Ast[kq * 4 + 1][m] = vv.y;
            Ast[kq * 4 + 2][m] = vv.z;
            Ast[kq * 4 + 3][m] = vv.w;
        }
        #pragma unroll
        for (int q = 0; q < 2; q++) {
            int idx = tid + 256 * q;
            if (idx < 16 * 32) {
                int k = idx >> 5, c = idx & 31;
                float w = W[(size_t)(kc + k) * N + n0 + c];
                Wd[k][c] = pack2(w, w);
            }
        }
        __syncthreads();

        #pragma unroll
        for (int kk = 0; kk < 16; kk++) {
            ULL a[2];
            a[0] = *reinterpret_cast<const ULL*>(&Ast[kk][r0]);
            a[1] = *reinterpret_cast<const ULL*>(&Ast[kk][r0 + 2]);
            ULL w[4];
            #pragma unroll
            for (int j = 0; j < 4; j++) w[j] = Wd[kk][c0 + j];
            #pragma unroll
            for (int i = 0; i < 2; i++)
                #pragma unroll
                for (int j = 0; j < 4; j++)
                    acc[i][j] = ffma2(a[i], w[j], acc[i][j]);
        }
        __syncthreads();
    }

    float bc[4], sA[4], sB[4];
    #pragma unroll
    for (int j = 0; j < 4; j++) {
        bc[j] = bias[n0 + c0 + j];
        float lo = amin[n0 + c0 + j], hi = amax[n0 + c0 + j];
        sA[j] = 0.5f * (hi - lo);
        sB[j] = 0.5f * (hi + lo);
    }

    #pragma unroll
    for (int i = 0; i < 2; i++) {
        float vlo[4], vhi[4];
        #pragma unroll
        for (int j = 0; j < 4; j++) unpack2(acc[i][j], vlo[j], vhi[j]);
        int row = m0 + r0 + 2 * i;
        #pragma unroll
        for (int h = 0; h < 2; h++) {
            float* vv = (h == 0) ? vlo : vhi;
            float ov[4];
            #pragma unroll
            for (int j = 0; j < 4; j++) {
                float x = tanhf(vv[j] + bc[j]);
                ov[j] = x * sA[j] + sB[j];
            }
            float4 o = {ov[0], ov[1], ov[2], ov[3]};
            *reinterpret_cast<float4*>(&C[(size_t)(row + h) * N + n0 + c0]) = o;
        }
    }
}

// =====================================================================================
// Persistent LSTM scan: 128 CTAs x 512 threads, split-K halves, cp.async staging,
// distributed flag barrier. ys written ROW-MAJOR (coalesced 16B groups).
// =====================================================================================
#define SCAN_SMEM (65536 + 65536 + 8192 + 9216 + 2048 + 64)

__device__ __forceinline__ void gbar(unsigned target) {
    __syncthreads();
    if (threadIdx.x == 0) {
        __threadfence();
        ((volatile unsigned*)g_arrive)[blockIdx.x] = target;
    }
    if (threadIdx.x < 128) {
        while (((volatile unsigned*)g_arrive)[threadIdx.x] < target) { __nanosleep(16); }
        __threadfence();
    }
    __syncthreads();
}

__global__ __launch_bounds__(512, 1)
void scan_kernel(const float* __restrict__ xg, const float* __restrict__ Wh,
                 const float* __restrict__ b,  const float* __restrict__ h0,
                 const float* __restrict__ c0,
                 float* __restrict__ ys, float* __restrict__ hOut,
                 float* __restrict__ cOut)
{
    extern __shared__ __align__(128) char smraw[];
    ULL   (*Wsm)[16]           = reinterpret_cast<ULL(*)[16]>(smraw);
    float (*Asm)[2][32][128]   = reinterpret_cast<float(*)[2][32][128]>(smraw + 65536);
    ULL   (*psm)[4]            = reinterpret_cast<ULL(*)[4]>(smraw + 131072);
    float (*zsm)[18]           = reinterpret_cast<float(*)[18]>(smraw + 139264);
    float (*csm)[4]            = reinterpret_cast<float(*)[4]>(smraw + 148480);
    float *bsm                 = reinterpret_cast<float*>(smraw + 150528);

    const int tid  = threadIdx.x;
    const int cb   = blockIdx.x;
    const int j0   = cb * 4;
    const int half = tid >> 8;
    const int s    = tid & 255;
    const int cp   = s & 7;
    const int rq   = s >> 3;
    const int cA   = 2 * cp;
    const int cBc  = 2 * cp + 1;
    const int zcA  = (cA  >> 2) * Hh + j0 + (cA  & 3);
    const int zcB  = (cBc >> 2) * Hh + j0 + (cBc & 3);
    const int kbase = half * 256;

    const unsigned base = ((volatile unsigned*)g_arrive)[cb];

    for (int idx = tid; idx < 512 * 16; idx += 512) {
        int k = idx >> 4, c = idx & 15;
        int zcol = (c >> 2) * Hh + j0 + (c & 3);
        float w = Wh[(size_t)k * G4 + zcol];
        Wsm[k][c] = pack2(w, w);
    }
    if (tid < 16) bsm[tid] = b[(tid >> 2) * Hh + j0 + (tid & 3)];
    {
        int r = tid >> 2, jj = tid & 3;
        csm[r][jj] = c0[r * Hh + j0 + jj];
    }
    for (int idx = cb * 512 + tid; idx < Hh * Bb; idx += 128 * 512) {
        int j = idx >> 7, r = idx & 127;
        g_hT[0][idx] = h0[r * Hh + j];
    }
    gbar(base + 1);

    for (int t = 0; t < Tt; t++) {
        const float* hs = g_hT[t & 1];
        float*       hd = g_hT[(t + 1) & 1];

        float xv[4][2];
        if (half == 0) {
            #pragma unroll
            for (int rr = 0; rr < 4; rr++) {
                size_t bi = ((size_t)(4 * rq + rr) * Tt + t) * G4;
                xv[rr][0] = __ldg(&xg[bi + zcA]);
                xv[rr][1] = __ldg(&xg[bi + zcB]);
            }
        }

        ULL acc00 = 0, acc01 = 0, acc10 = 0, acc11 = 0;

        auto stage = [&](int i, int buf) {
            #pragma unroll
            for (int q = 0; q < 4; q++) {
                int f  = tid + 512 * q;
                int hf = f >> 10;
                int u  = f & 1023;
                int k  = u >> 5, c = u & 31;
                CP16(sptr(&Asm[buf][hf][k][c * 4]),
                     hs + ((hf * 256 + i * 32 + k) << 7) + c * 4);
            }
        };

        stage(0, 0);
        CP_COMMIT();
        for (int i = 0; i < 8; i++) {
            if (i < 7) { stage(i + 1, (i + 1) & 1); CP_COMMIT(); CP_WAIT1(); }
            else       { CP_WAIT0(); }
            __syncthreads();
            const int buf = i & 1;
            #pragma unroll
            for (int kk = 0; kk < 32; kk++) {
                ulonglong2 a = *reinterpret_cast<const ulonglong2*>(&Asm[buf][half][kk][4 * rq]);
                ulonglong2 w = *reinterpret_cast<const ulonglong2*>(&Wsm[kbase + i * 32 + kk][cA]);
                acc00 = ffma2(a.x, w.x, acc00);
                acc01 = ffma2(a.x, w.y, acc01);
                acc10 = ffma2(a.y, w.x, acc10);
                acc11 = ffma2(a.y, w.y, acc11);
            }
            __syncthreads();
        }

        if (half == 1) {
            psm[s][0] = acc00; psm[s][1] = acc01;
            psm[s][2] = acc10; psm[s][3] = acc11;
        }
        __syncthreads();
        if (half == 0) {
            acc00 = add2(acc00, psm[s][0]);
            acc01 = add2(acc01, psm[s][1]);
            acc10 = add2(acc10, psm[s][2]);
            acc11 = add2(acc11, psm[s][3]);
            float bA = bsm[cA], bB = bsm[cBc];
            float lo, hi;
            unpack2(acc00, lo, hi);
            zsm[4 * rq + 0][cA]  = lo + xv[0][0] + bA;
            zsm[4 * rq + 1][cA]  = hi + xv[1][0] + bA;
            unpack2(acc01, lo, hi);
            zsm[4 * rq + 0][cBc] = lo + xv[0][1] + bB;
            zsm[4 * rq + 1][cBc] = hi + xv[1][1] + bB;
            unpack2(acc10, lo, hi);
            zsm[4 * rq + 2][cA]  = lo + xv[2][0] + bA;
            zsm[4 * rq + 3][cA]  = hi + xv[3][0] + bA;
            unpack2(acc11, lo, hi);
            zsm[4 * rq + 2][cBc] = lo + xv[2][1] + bB;
            zsm[4 * rq + 3][cBc] = hi + xv[3][1] + bB;
        }
        __syncthreads();

        {
            int r = tid >> 2, jj = tid & 3;
            float zi = zsm[r][0  + jj];
            float zf = zsm[r][4  + jj];
            float zg = zsm[r][8  + jj];
            float zo = zsm[r][12 + jj];
            float cc = csm[r][jj];
            float cn = sigmoidf_(zf) * cc + sigmoidf_(zi) * tanhf(zg);
            float hn = sigmoidf_(zo) * tanhf(cn);
            csm[r][jj] = cn;
            hd[(j0 + jj) * Bb + r] = hn;
            ys[((size_t)r * Tt + t) * Hh + j0 + jj] = hn;   // 16B-coalesced per 4 threads
            if (t == Tt - 1) hOut[r * Hh + j0 + jj] = hn;
        }

        gbar(base + 2 + (unsigned)t);
    }

    {
        int r = tid >> 2, jj = tid & 3;
        cOut[r * Hh + j0 + jj] = csm[r][jj];
    }
}

// =====================================================================================
extern "C" void kernel_launch(void* const* d_in, const int* in_sizes, int n_in,
                              void* d_out, int out_size)
{
    const float* obs  = (const float*)d_in[0];
    const float* h0   = (const float*)d_in[1];
    const float* c0   = (const float*)d_in[2];
    const float* Wx   = (const float*)d_in[3];
    const float* Wh   = (const float*)d_in[4];
    const float* b    = (const float*)d_in[5];
    const float* W1   = (const float*)d_in[6];
    const float* b1   = (const float*)d_in[7];
    const float* W2   = (const float*)d_in[8];
    const float* b2   = (const float*)d_in[9];
    const float* Wo   = (const float*)d_in[10];
    const float* bo   = (const float*)d_in[11];
    const float* amin = (const float*)d_in[12];
    const float* amax = (const float*)d_in[13];

    float* out        = (float*)d_out;
    float* out_action = out;
    float* out_h      = out + (size_t)MTOT * NACT;
    float* out_c      = out_h + (size_t)Bb * Hh;

    float *p_xg, *p_ys, *p_ysT, *p_a1T, *p_a2, *p_obsT;
    ULL   *p_Wxp, *p_W1p, *p_W2p;
    cudaGetSymbolAddress((void**)&p_xg,   g_xg);
    cudaGetSymbolAddress((void**)&p_ys,   g_ys);
    cudaGetSymbolAddress((void**)&p_ysT,  g_ysT);
    cudaGetSymbolAddress((void**)&p_a1T,  g_a1T);
    cudaGetSymbolAddress((void**)&p_a2,   g_a2);
    cudaGetSymbolAddress((void**)&p_obsT, g_obsT);
    cudaGetSymbolAddress((void**)&p_Wxp,  g_Wxp);
    cudaGetSymbolAddress((void**)&p_W1p,  g_W1p);
    cudaGetSymbolAddress((void**)&p_W2p,  g_W2p);

    cudaFuncSetAttribute(scan_kernel,
                         cudaFuncAttributeMaxDynamicSharedMemorySize, SCAN_SMEM);

    // ---- pre-pass: transpose obs, dup-pack weights ----
    {
        dim3 g(MTOT / 32, NOBS / 32);
        transpose_k<<<g, 256>>>(obs, p_obsT, MTOT, NOBS);
        pack_dup<<<(NOBS * G4 + 255) / 256, 256>>>(Wx, p_Wxp, NOBS * G4);
        pack_dup<<<(Hh * Hh + 255) / 256, 256>>>(W1, p_W1p, Hh * Hh);
        pack_dup<<<(Hh * Hh + 255) / 256, 256>>>(W2, p_W2p, Hh * Hh);
    }
    // 1) xg = obs @ Wx   (row-major out)
    {
        dim3 grid(G4 / 128, MTOT / 128);
        gemm_p<0, 0><<<grid, 256>>>(p_obsT, p_Wxp, nullptr, p_xg, MTOT, G4, NOBS);
    }
    // 2) LSTM scan -> ys (row-major)
    scan_kernel<<<128, 512, SCAN_SMEM>>>(p_xg, Wh, b, h0, c0, p_ys, out_h, out_c);
    // 2b) transpose ys -> ysT for MLP1
    {
        dim3 g(MTOT / 32, Hh / 32);
        transpose_k<<<g, 256>>>(p_ys, p_ysT, MTOT, Hh);
    }
    // 3) a1T = relu(ys @ W1 + b1)^T
    {
        dim3 grid(Hh / 128, MTOT / 128);
        gemm_p<1, 1><<<grid, 256>>>(p_ysT, p_W1p, b1, p_a1T, MTOT, Hh, Hh);
    }
    // 4) a2 = relu(a1 @ W2 + b2)   (row-major out)
    {
        dim3 grid(Hh / 128, MTOT / 128);
        gemm_p<1, 0><<<grid, 256>>>(p_a1T, p_W2p, b2, p_a2, MTOT, Hh, Hh);
    }
    // 5) action head
    {
        dim3 grid(NACT / 32, MTOT / 128);
        gemm_head<<<grid, 256>>>(p_a2, Wo, bo, out_action, MTOT, NACT, Hh, amin, amax);
    }
    (void)in_sizes; (void)n_in; (void)out_size;
}